// round 3
// baseline (speedup 1.0000x reference)
#include <cuda_runtime.h>
#include <cuda_bf16.h>
#include <stdint.h>

#define BATCH 8
#define SEQ   2048
#define DIM   2048
#define DHALF 1024
#define NTOT  (BATCH*DHALF)   /* 8192 */

#define BM 128
#define BN 128
#define BK 32
#define KITERS (SEQ/BK)       /* 64 */
#define NSTAGE 3
#define PITCH_H 40            /* 32 data halves + 8 pad */
#define PITCH_B 80
#define TILE_BYTES (128*PITCH_B)          /* 10240 per matrix */
#define STAGE_BYTES (2*TILE_BYTES)        /* 20480 */
#define SMEM_TOTAL (NSTAGE*STAGE_BYTES)   /* 61440 */

__device__ __nv_bfloat16 g_wb[(size_t)SEQ * SEQ];       /* W bf16, [s][t] K-major */
__device__ __nv_bfloat16 g_gateT[(size_t)NTOT * SEQ];   /* LN(gate)^T, [b*1024+d][t] */

/* ---------------- helpers ---------------- */

static __device__ __forceinline__ uint32_t smem_u32(const void* p) {
    return (uint32_t)__cvta_generic_to_shared(p);
}

static __device__ __forceinline__ void cp_async16(uint32_t dst, const void* src) {
    asm volatile("cp.async.cg.shared.global [%0], [%1], 16;" :: "r"(dst), "l"(src));
}

static __device__ __forceinline__ void ldsm_x4(uint32_t* r, uint32_t addr) {
    asm volatile("ldmatrix.sync.aligned.m8n8.x4.shared.b16 {%0,%1,%2,%3}, [%4];"
                 : "=r"(r[0]), "=r"(r[1]), "=r"(r[2]), "=r"(r[3]) : "r"(addr));
}

static __device__ __forceinline__ void mma_bf16(float* c, const uint32_t* a,
                                                uint32_t b0, uint32_t b1) {
    asm volatile(
        "mma.sync.aligned.m16n8k16.row.col.f32.bf16.bf16.f32 "
        "{%0,%1,%2,%3}, {%4,%5,%6,%7}, {%8,%9}, {%0,%1,%2,%3};"
        : "+f"(c[0]), "+f"(c[1]), "+f"(c[2]), "+f"(c[3])
        : "r"(a[0]), "r"(a[1]), "r"(a[2]), "r"(a[3]), "r"(b0), "r"(b1));
}

/* ---------------- Kernel 1: W fp32 -> bf16 ---------------- */

__global__ void __launch_bounds__(256) k_wconv(const float* __restrict__ w) {
    size_t i = (size_t)blockIdx.x * blockDim.x + threadIdx.x;  /* over float4 */
    float4 v = ((const float4*)w)[i];
    __nv_bfloat162* o = (__nv_bfloat162*)g_wb;
    o[2 * i]     = __floats2bfloat162_rn(v.x, v.y);
    o[2 * i + 1] = __floats2bfloat162_rn(v.z, v.w);
}

/* ------- Kernel 2: LayerNorm(gate) + transpose to [n][t] bf16 ------- */

__global__ void __launch_bounds__(256) k_ln_t(const float* __restrict__ x,
                                              const float* __restrict__ ln_scale,
                                              const float* __restrict__ ln_bias) {
    __shared__ float s_mu[32];
    __shared__ float s_rs[32];
    __shared__ float tile[32][33];

    int b = blockIdx.y;
    int t0 = blockIdx.x * 32;
    int tid = threadIdx.x, wid = tid >> 5, lid = tid & 31;

    const float* gate = x + (size_t)b * SEQ * DIM + DHALF;

    for (int r = wid; r < 32; r += 8) {
        const float* row = gate + (size_t)(t0 + r) * DIM;
        float s = 0.f, s2 = 0.f;
#pragma unroll 8
        for (int d = lid; d < DHALF; d += 32) {
            float v = row[d];
            s += v; s2 += v * v;
        }
#pragma unroll
        for (int o = 16; o > 0; o >>= 1) {
            s  += __shfl_xor_sync(0xFFFFFFFFu, s, o);
            s2 += __shfl_xor_sync(0xFFFFFFFFu, s2, o);
        }
        if (lid == 0) {
            float mu = s * (1.f / DHALF);
            float var = s2 * (1.f / DHALF) - mu * mu;
            s_mu[r] = mu;
            s_rs[r] = rsqrtf(var + 1e-5f);
        }
    }
    __syncthreads();

    for (int c = 0; c < DHALF / 32; ++c) {
        int dbase = c * 32;
#pragma unroll
        for (int i = 0; i < 4; ++i) {
            int tl = wid + i * 8;
            int dl = lid;
            float v = gate[(size_t)(t0 + tl) * DIM + dbase + dl];
            v = (v - s_mu[tl]) * s_rs[tl] * ln_scale[dbase + dl] + ln_bias[dbase + dl];
            tile[tl][dl] = v;
        }
        __syncthreads();
#pragma unroll
        for (int i = 0; i < 4; ++i) {
            int dl = wid + i * 8;
            int tl = lid;
            g_gateT[(size_t)(b * DHALF + dbase + dl) * SEQ + t0 + tl] =
                __float2bfloat16(tile[tl][dl]);
        }
        __syncthreads();
    }
}

/* ------- Kernel 3: mma.sync GEMM + fused gating epilogue ------- */

static __device__ __forceinline__ void load_stage(uint32_t st,
                                                  const __nv_bfloat16* gA,
                                                  const __nv_bfloat16* gB,
                                                  int kb, int tid) {
#pragma unroll
    for (int i = 0; i < 2; ++i) {
        int t = tid + i * 256;
        int row = t >> 2, seg = t & 3;
        cp_async16(st + (uint32_t)(row * PITCH_B + seg * 16),
                   gA + (size_t)row * SEQ + kb + seg * 8);
    }
#pragma unroll
    for (int i = 0; i < 2; ++i) {
        int t = tid + i * 256;
        int row = t >> 2, seg = t & 3;
        cp_async16(st + TILE_BYTES + (uint32_t)(row * PITCH_B + seg * 16),
                   gB + (size_t)row * SEQ + kb + seg * 8);
    }
}

__global__ void __launch_bounds__(256, 2) k_gemm_epi(const float* __restrict__ x,
                                                     const float* __restrict__ proj_b,
                                                     float* __restrict__ out) {
    extern __shared__ char smem[];
    uint32_t sb = smem_u32(smem);
    int tid = threadIdx.x;
    int wid = tid >> 5, lane = tid & 31;
    int wm = wid >> 1, wn = wid & 1;          /* 4 x 2 warp grid, tile 32x64 */
    int m_tile = blockIdx.y, n_tile = blockIdx.x;

    const __nv_bfloat16* gA = g_wb + (size_t)m_tile * BM * SEQ;
    const __nv_bfloat16* gB = g_gateT + (size_t)n_tile * BN * SEQ;

    float acc[2][8][4];
#pragma unroll
    for (int mi = 0; mi < 2; ++mi)
#pragma unroll
        for (int ni = 0; ni < 8; ++ni)
#pragma unroll
            for (int j = 0; j < 4; ++j) acc[mi][ni][j] = 0.f;

    /* precompute ldmatrix smem offsets (within a stage) */
    int a_row = wm * 32 + (lane & 15);
    int a_colh = (lane >> 4) << 3;                       /* 0 or 8 halves */
    int b_row = wn * 64 + (lane & 7) + ((lane & 16) ? 8 : 0);
    int b_colh = (lane & 8);                             /* 0 or 8 halves */

    /* prologue: stages 0,1 */
    load_stage(sb, gA, gB, 0, tid);
    asm volatile("cp.async.commit_group;" ::: "memory");
    load_stage(sb + STAGE_BYTES, gA, gB, BK, tid);
    asm volatile("cp.async.commit_group;" ::: "memory");

    for (int it = 0; it < KITERS; ++it) {
        asm volatile("cp.async.wait_group 1;" ::: "memory");
        __syncthreads();

        /* prefetch stage it+2 (buffer consumed at it-1; all warps past it-1 now) */
        if (it + 2 < KITERS) {
            uint32_t st = sb + (uint32_t)((it + 2) % NSTAGE) * STAGE_BYTES;
            load_stage(st, gA, gB, (it + 2) * BK, tid);
        }
        asm volatile("cp.async.commit_group;" ::: "memory");

        uint32_t sA = sb + (uint32_t)(it % NSTAGE) * STAGE_BYTES;
        uint32_t sB = sA + TILE_BYTES;

#pragma unroll
        for (int ks = 0; ks < 2; ++ks) {
            uint32_t a[2][4], bf[4][4];
#pragma unroll
            for (int mi = 0; mi < 2; ++mi)
                ldsm_x4(a[mi], sA + (uint32_t)((a_row + mi * 16) * PITCH_B +
                                               (ks * 16 + a_colh) * 2));
#pragma unroll
            for (int nj = 0; nj < 4; ++nj)
                ldsm_x4(bf[nj], sB + (uint32_t)((b_row + nj * 16) * PITCH_B +
                                                (ks * 16 + b_colh) * 2));
#pragma unroll
            for (int mi = 0; mi < 2; ++mi)
#pragma unroll
                for (int nj = 0; nj < 4; ++nj) {
                    mma_bf16(acc[mi][2 * nj],     a[mi], bf[nj][0], bf[nj][1]);
                    mma_bf16(acc[mi][2 * nj + 1], a[mi], bf[nj][2], bf[nj][3]);
                }
        }
    }

    /* ---- epilogue: out[b,s,d] = (acc + proj_b[s]) * res[b,s,d] ---- */
    int n_base = n_tile * BN;
    int b = n_base >> 10;          /* BN=128 divides 1024 */
    int d_base = (n_base & 1023) + wn * 64;
    int qr = lane >> 2, qc = (lane & 3) * 2;

#pragma unroll
    for (int mi = 0; mi < 2; ++mi) {
        int s0 = m_tile * BM + wm * 32 + mi * 16 + qr;
        float pb0 = proj_b[s0];
        float pb1 = proj_b[s0 + 8];
        const float* res0 = x + (size_t)b * SEQ * DIM + (size_t)s0 * DIM;
        const float* res1 = res0 + 8 * DIM;
        float* out0 = out + (size_t)b * SEQ * DHALF + (size_t)s0 * DHALF;
        float* out1 = out0 + 8 * DHALF;
#pragma unroll
        for (int ni = 0; ni < 8; ++ni) {
            int d = d_base + ni * 8 + qc;
            float2 r0 = *(const float2*)(res0 + d);
            float2 r1 = *(const float2*)(res1 + d);
            float2 o0, o1;
            o0.x = (acc[mi][ni][0] + pb0) * r0.x;
            o0.y = (acc[mi][ni][1] + pb0) * r0.y;
            o1.x = (acc[mi][ni][2] + pb1) * r1.x;
            o1.y = (acc[mi][ni][3] + pb1) * r1.y;
            *(float2*)(out0 + d) = o0;
            *(float2*)(out1 + d) = o1;
        }
    }
}

/* ---------------- launch ---------------- */

extern "C" void kernel_launch(void* const* d_in, const int* in_sizes, int n_in,
                              void* d_out, int out_size) {
    (void)in_sizes; (void)n_in; (void)out_size;
    const float* x   = (const float*)d_in[0];
    const float* w   = (const float*)d_in[1];
    const float* pb  = (const float*)d_in[2];
    const float* lns = (const float*)d_in[3];
    const float* lnb = (const float*)d_in[4];
    float* out = (float*)d_out;

    cudaFuncSetAttribute(k_gemm_epi, cudaFuncAttributeMaxDynamicSharedMemorySize,
                         SMEM_TOTAL);

    k_wconv<<<(SEQ * SEQ / 4) / 256, 256>>>(w);
    k_ln_t<<<dim3(SEQ / 32, BATCH), 256>>>(x, lns, lnb);
    k_gemm_epi<<<dim3(NTOT / BN, SEQ / BM), 256, SMEM_TOTAL>>>(x, pb, out);
}